// round 7
// baseline (speedup 1.0000x reference)
#include <cuda_runtime.h>
#include <math.h>

#define N_NODES  100000
#define N_EDGES  400000
#define N_GRAPHS 4000
#define D        70
#define NP       240
#define KDIM     280
#define BCAP     32           // bucket capacity (P(deg>32) ~ e^-44 for Poisson(4))

// ---------------- scratch (device globals) ---------------------------------
__device__ float g_h[N_NODES * D];
__device__ float g_agg[N_NODES * 4 * D];      // [mean|min|max|std], K=280
__device__ float g_amp[N_NODES];
__device__ int   g_cnt[N_NODES];
__device__ int2  g_bucket[N_NODES * BCAP];    // (edge id, src node)
__device__ float g_gsum[N_GRAPHS * D];
__device__ float g_gcnt[N_GRAPHS];
// packed tf32 weights, pair-permuted for LDS.64 frag loads:
// float2 index (per layer): ((kt*5 + g)*240 + col)*4 + l
//   holds (W[kt*40+g*8+l][col], W[kt*40+g*8+4+l][col])
__device__ float g_w3[4 * KDIM * NP];

__constant__ int c_atom_off[9] = {0, 119, 124, 136, 148, 158, 164, 170, 172};

#define AVG_LOG_F 1.2465355243460002f
#define INV_BN    0.9999950000374997f

__device__ __forceinline__ float to_tf32(float x) {
    unsigned u;
    asm("cvt.rna.tf32.f32 %0, %1;" : "=r"(u) : "f"(x));
    return __uint_as_float(u);
}

__device__ __forceinline__ void mma_tf32(float c[4], unsigned a0, unsigned a1,
                                         unsigned a2, unsigned a3,
                                         unsigned b0, unsigned b1) {
    asm volatile(
        "mma.sync.aligned.m16n8k8.row.col.f32.tf32.tf32.f32 "
        "{%0,%1,%2,%3}, {%4,%5,%6,%7}, {%8,%9}, {%0,%1,%2,%3};\n"
        : "+f"(c[0]), "+f"(c[1]), "+f"(c[2]), "+f"(c[3])
        : "r"(a0), "r"(a1), "r"(a2), "r"(a3), "r"(b0), "r"(b1));
}

// ------- launch 1: atom encoder + zero init + W3 pack (all independent) ----
__global__ void init_kernel(const int* __restrict__ x, const float* __restrict__ emb,
                            const float* __restrict__ W) {
    int flat = threadIdx.y * 70 + threadIdx.x;
    int gtid = blockIdx.x * 280 + flat;
    if (gtid < N_NODES) g_cnt[gtid] = 0;
    if (gtid < N_GRAPHS * D) g_gsum[gtid] = 0.f;
    if (gtid < N_GRAPHS) g_gcnt[gtid] = 0.f;

    // W3 pack into pair-permuted tf32 layout
    if (gtid < 134400) {                      // 4 layers * 33600 float2
        int layer = gtid / 33600;
        int rem = gtid - layer * 33600;
        int kt = rem / 4800; rem -= kt * 4800;
        int g = rem / 960;   rem -= g * 960;
        int col = rem >> 2;
        int l = rem & 3;
        int half = col / 120;
        int cr = col - half * 120;
        int tile = cr >> 3;
        int u = cr & 7;
        int p = tile / 5;
        int jb = tile - p * 5;
        int j = half * 40 + jb * 8 + u;
        int kx = kt * 40 + g * 8 + l;
        float vx = 0.f, vy = 0.f;
        if (j < 70) {
            const float* Wl = W + (size_t)layer * 840 * 70;
            vx = to_tf32(Wl[(size_t)(p * KDIM + kx) * 70 + j]);
            vy = to_tf32(Wl[(size_t)(p * KDIM + kx + 4) * 70 + j]);
        }
        g_w3[gtid * 2]     = vx;
        g_w3[gtid * 2 + 1] = vy;
    }

    int n = blockIdx.x * blockDim.y + threadIdx.y;
    int f = threadIdx.x;
    if (n >= N_NODES) return;
    float s = 0.f;
#pragma unroll
    for (int j = 0; j < 9; j++) {
        int idx = x[n * 9 + j] + c_atom_off[j];
        s += emb[idx * D + f];
    }
    g_h[n * D + f] = s;
}

// ------- launch 2: direct bucket scatter -----------------------------------
__global__ void scatter_kernel(const int* __restrict__ ei) {
    int e = blockIdx.x * blockDim.x + threadIdx.x;
    if (e < N_EDGES) {
        int d = ei[N_EDGES + e];
        int s = ei[e];
        int p = atomicAdd(&g_cnt[d], 1);
        if (p < BCAP) g_bucket[(size_t)d * BCAP + p] = make_int2(e, s);
    }
}

// ------- per-node aggregation (one warp per node) --------------------------
// float2-vectorized: lane covers feats {2l, 2l+1}; lanes 0..2 also {64+2l, 65+2l}
__global__ void agg_kernel(const float* __restrict__ ea) {
    int gtid = blockIdx.x * blockDim.x + threadIdx.x;
    int node = gtid >> 5;
    int lane = gtid & 31;
    if (node >= N_NODES) return;

    const float2* hrow = (const float2*)(g_h + (size_t)node * D);
    float2 hm = hrow[lane];
    float2 ht = make_float2(0.f, 0.f);
    if (lane < 3) ht = hrow[32 + lane];

    int cnt0 = g_cnt[node];
    int cnt = (cnt0 < BCAP) ? cnt0 : BCAP;
    const int2* bkt = g_bucket + (size_t)node * BCAP;

    float2 s  = make_float2(0.f, 0.f), q  = make_float2(0.f, 0.f);
    float2 mn = make_float2(3.4e38f, 3.4e38f), mx = make_float2(0.f, 0.f);
    float2 st = make_float2(0.f, 0.f), qt = make_float2(0.f, 0.f);
    float2 mnt = make_float2(3.4e38f, 3.4e38f), mxt = make_float2(0.f, 0.f);

    int2 es = make_int2(0, 0);
    if (cnt > 0) es = bkt[0];
    for (int p = 0; p < cnt; p++) {
        const float2* hs = (const float2*)(g_h + (size_t)es.y * D);
        const float2* er = (const float2*)(ea + (size_t)es.x * D);
        float2 a = hs[lane];
        float2 b2 = er[lane];
        float2 at = make_float2(0.f, 0.f), bt = make_float2(0.f, 0.f);
        if (lane < 3) { at = hs[32 + lane]; bt = er[32 + lane]; }
        if (p + 1 < cnt) es = bkt[p + 1];   // prefetch next (edge, src)

        float m0 = fmaxf(hm.x + a.x + b2.x, 0.f);
        float m1 = fmaxf(hm.y + a.y + b2.y, 0.f);
        s.x += m0; q.x += m0 * m0; mn.x = fminf(mn.x, m0); mx.x = fmaxf(mx.x, m0);
        s.y += m1; q.y += m1 * m1; mn.y = fminf(mn.y, m1); mx.y = fmaxf(mx.y, m1);
        if (lane < 3) {
            float t0 = fmaxf(ht.x + at.x + bt.x, 0.f);
            float t1 = fmaxf(ht.y + at.y + bt.y, 0.f);
            st.x += t0; qt.x += t0 * t0; mnt.x = fminf(mnt.x, t0); mxt.x = fmaxf(mxt.x, t0);
            st.y += t1; qt.y += t1 * t1; mnt.y = fminf(mnt.y, t1); mxt.y = fmaxf(mxt.y, t1);
        }
    }
    float cf = (cnt > 0) ? (float)cnt : 1.f;
    float inv = 1.f / cf;

    float2 me = make_float2(s.x * inv, s.y * inv);
    float2 sd;
    sd.x = sqrtf(fmaxf(q.x * inv - me.x * me.x, 0.f) + 1e-5f);
    sd.y = sqrtf(fmaxf(q.y * inv - me.y * me.y, 0.f) + 1e-5f);
    float2 met = make_float2(st.x * inv, st.y * inv);
    float2 sdt;
    sdt.x = sqrtf(fmaxf(qt.x * inv - met.x * met.x, 0.f) + 1e-5f);
    sdt.y = sqrtf(fmaxf(qt.y * inv - met.y * met.y, 0.f) + 1e-5f);
    if (cnt == 0) {
        mn = make_float2(0.f, 0.f); mx = make_float2(0.f, 0.f);
        mnt = make_float2(0.f, 0.f); mxt = make_float2(0.f, 0.f);
    }

    float2* arow = (float2*)(g_agg + (size_t)node * (4 * D));
    arow[lane]            = me;
    arow[35 + lane]       = mn;
    arow[70 + lane]       = mx;
    arow[105 + lane]      = sd;
    if (lane < 3) {
        arow[32 + lane]       = met;
        arow[35 + 32 + lane]  = mnt;
        arow[70 + 32 + lane]  = mxt;
        arow[105 + 32 + lane] = sdt;
    }
    if (lane == 0) g_amp[node] = logf(cf + 1.f) / AVG_LOG_F;
}

// ---------------- TF32 tensor-core GEMM + epilogue -------------------------
// [128 x 280] @ [280 x 240] per block; 16 warps: wm=wid&7 (16-row tile),
// wn=wid>>3 (120-col half). B sub-tiled 2 k-groups at a time (smem 35.8KB).
#define GM 128
__global__ __launch_bounds__(512, 1)
void gemm_kernel(int layer,
                 const float* __restrict__ b,
                 const float* __restrict__ gamma, const float* __restrict__ beta) {
    __shared__ float2 As2[5 * GM * 4];    // [g][row][l] = (A[r][8g+l], A[r][8g+4+l])
    __shared__ float2 Bs2[2 * 240 * 4];   // [gg][col][l], gg = g - gs
    const float* W3 = g_w3 + (size_t)layer * (KDIM * NP);
    int t = threadIdx.x;
    int lane = t & 31, wid = t >> 5;
    int wm = wid & 7, wn = wid >> 3;
    int row0 = blockIdx.x * GM;

    float c[15][4];
#pragma unroll
    for (int i = 0; i < 15; i++)
#pragma unroll
        for (int r = 0; r < 4; r++) c[i][r] = 0.f;

    float* As_f = (float*)As2;
    float4* Bs4 = (float4*)Bs2;

    for (int kt = 0; kt < 7; kt++) {
        int k0 = kt * 40;
        // A fill: GM rows x 10 float4 (k-major), scatter into pair layout
        for (int idx = t; idx < GM * 10; idx += 512) {
            int r = idx / 10, qq = idx - r * 10;
            int gr = row0 + r;
            float4 v = make_float4(0.f, 0.f, 0.f, 0.f);
            if (gr < N_NODES)
                v = *(const float4*)(g_agg + (size_t)gr * KDIM + k0 + qq * 4);
            int g = qq >> 1, sslot = qq & 1;
            int base = (g * GM + r) * 8 + sslot;
            As_f[base + 0] = to_tf32(v.x);
            As_f[base + 2] = to_tf32(v.y);
            As_f[base + 4] = to_tf32(v.z);
            As_f[base + 6] = to_tf32(v.w);
        }
        for (int gs = 0; gs < 5; gs += 2) {
            int ng = (gs + 2 <= 5) ? 2 : 1;
            // B fill: straight float4 copy (prepacked layout == smem layout)
            const float4* Wg = (const float4*)(W3 + ((size_t)(kt * 5 + gs) * 960 * 2));
            int nf4 = ng * 480;
            for (int idx = t; idx < nf4; idx += 512) Bs4[idx] = Wg[idx];
            __syncthreads();
#pragma unroll
            for (int gg = 0; gg < 2; gg++) {
                if (gg >= ng) break;
                int g = gs + gg;
                float2 A0 = As2[(g * GM + wm * 16 + (lane >> 2)) * 4 + (lane & 3)];
                float2 A1 = As2[(g * GM + wm * 16 + 8 + (lane >> 2)) * 4 + (lane & 3)];
                unsigned a0 = __float_as_uint(A0.x), a1 = __float_as_uint(A1.x);
                unsigned a2 = __float_as_uint(A0.y), a3 = __float_as_uint(A1.y);
#pragma unroll
                for (int tile = 0; tile < 15; tile++) {
                    float2 Bv = Bs2[(gg * 240 + wn * 120 + tile * 8 + (lane >> 2)) * 4 + (lane & 3)];
                    mma_tf32(c[tile], a0, a1, a2, a3,
                             __float_as_uint(Bv.x), __float_as_uint(Bv.y));
                }
            }
            __syncthreads();
        }
    }

    // epilogue: combine 3 panels with amp, bias, BN, relu, residual
    int r0 = row0 + wm * 16 + (lane >> 2);
    int r1 = r0 + 8;
    float amp0 = (r0 < N_NODES) ? g_amp[r0] : 1.f;
    float amp1 = (r1 < N_NODES) ? g_amp[r1] : 1.f;
#pragma unroll
    for (int jb = 0; jb < 5; jb++) {
#pragma unroll
        for (int cc = 0; cc < 2; cc++) {
            int j = wn * 40 + jb * 8 + (lane & 3) * 2 + cc;
            if (j < 70) {
                float bj = b[j], gj = gamma[j], btj = beta[j];
                if (r0 < N_NODES) {
                    float comb = c[jb][cc] + amp0 * c[5 + jb][cc] + c[10 + jb][cc] / amp0;
                    float hn = fmaxf((comb + bj) * INV_BN * gj + btj, 0.f);
                    g_h[(size_t)r0 * D + j] += hn;
                }
                if (r1 < N_NODES) {
                    float comb = c[jb][2 + cc] + amp1 * c[5 + jb][2 + cc] + c[10 + jb][2 + cc] / amp1;
                    float hn = fmaxf((comb + bj) * INV_BN * gj + btj, 0.f);
                    g_h[(size_t)r1 * D + j] += hn;
                }
            }
        }
    }
}

// ---------------- global mean pool -----------------------------------------
__global__ void pool_kernel(const int* __restrict__ batch) {
    int n = blockIdx.x * blockDim.y + threadIdx.y;
    int f = threadIdx.x;
    if (n >= N_NODES) return;
    int gi = batch[n];
    atomicAdd(&g_gsum[gi * D + f], g_h[(size_t)n * D + f]);
    if (f == 0) atomicAdd(&g_gcnt[gi], 1.f);
}

// ---------------- final MLP 70->35->17->1 ----------------------------------
__global__ void mlp_kernel(const float* __restrict__ w1, const float* __restrict__ b1,
                           const float* __restrict__ w2, const float* __restrict__ b2,
                           const float* __restrict__ w3, const float* __restrict__ b3,
                           float* __restrict__ out) {
    __shared__ float sg[70], t1[35], t2[17];
    int gi = blockIdx.x;
    int t = threadIdx.x;
    if (t < 70) {
        float cdenom = fmaxf(g_gcnt[gi], 1.f);
        sg[t] = g_gsum[gi * D + t] / cdenom;
    }
    __syncthreads();
    if (t < 35) {
        float s = b1[t];
        for (int k = 0; k < 70; k++) s += sg[k] * w1[k * 35 + t];
        t1[t] = fmaxf(s, 0.f);
    }
    __syncthreads();
    if (t < 17) {
        float s = b2[t];
        for (int k = 0; k < 35; k++) s += t1[k] * w2[k * 17 + t];
        t2[t] = fmaxf(s, 0.f);
    }
    __syncthreads();
    if (t == 0) {
        float s = b3[0];
        for (int k = 0; k < 17; k++) s += t2[k] * w3[k];
        out[gi] = s;
    }
}

// ---------------- launcher --------------------------------------------------
extern "C" void kernel_launch(void* const* d_in, const int* in_sizes, int n_in,
                              void* d_out, int out_size) {
    const int*   x      = (const int*)d_in[0];
    const int*   ei     = (const int*)d_in[1];
    const float* ea     = (const float*)d_in[2];
    const int*   batch  = (const int*)d_in[3];
    const float* emb    = (const float*)d_in[4];
    const float* post_w = (const float*)d_in[5];
    const float* post_b = (const float*)d_in[6];
    const float* gamma  = (const float*)d_in[7];
    const float* beta   = (const float*)d_in[8];
    const float* w1 = (const float*)d_in[9];
    const float* b1 = (const float*)d_in[10];
    const float* w2 = (const float*)d_in[11];
    const float* b2 = (const float*)d_in[12];
    const float* w3 = (const float*)d_in[13];
    const float* b3 = (const float*)d_in[14];
    float* out = (float*)d_out;

    init_kernel<<<(N_NODES + 3) / 4, dim3(70, 4)>>>(x, emb, post_w);   // 1
    scatter_kernel<<<(N_EDGES + 255) / 256, 256>>>(ei);                // 2

    for (int l = 0; l < 4; l++) {
        agg_kernel<<<(N_NODES * 32 + 255) / 256, 256>>>(ea);           // 3 (l=0)
        gemm_kernel<<<(N_NODES + GM - 1) / GM, 512>>>(                 // 4 (l=0) <- profiled
            l, post_b + l * 70, gamma + l * 70, beta + l * 70);
    }

    pool_kernel<<<(N_NODES + 3) / 4, dim3(70, 4)>>>(batch);
    mlp_kernel<<<N_GRAPHS, 70>>>(w1, b1, w2, b2, w3, b3, out);
}

// round 8
// speedup vs baseline: 1.3793x; 1.3793x over previous
#include <cuda_runtime.h>
#include <math.h>

#define N_NODES  100000
#define N_EDGES  400000
#define N_GRAPHS 4000
#define D        70
#define NP       240
#define KDIM     280
#define BCAP     32           // bucket capacity (P(deg>32) ~ e^-44 for Poisson(4))
#define NPAD     100032       // padded rows (1563 * 64)

// ---------------- scratch (device globals) ---------------------------------
__device__ float g_h[N_NODES * D];
// agg in pair-permuted tf32 layout: value of logical k stored at posk(k) within
// each 280-float row; rows >= N_NODES stay zero (device globals zero-init).
__device__ __align__(16) float g_agg[NPAD * KDIM];
__device__ float g_amp[N_NODES];
__device__ int   g_cnt[N_NODES];
__device__ int2  g_bucket[N_NODES * BCAP];    // (edge id, src node)
__device__ float g_gsum[N_GRAPHS * D];
__device__ float g_gcnt[N_GRAPHS];
// packed tf32 weights, pair-permuted for LDS.64 frag loads:
// float2 index (per layer): ((kt*5 + g)*240 + col)*4 + l
//   holds (W[kt*40+g*8+l][col], W[kt*40+g*8+4+l][col])
__device__ __align__(16) float g_w3[4 * KDIM * NP];

__constant__ int c_atom_off[9] = {0, 119, 124, 136, 148, 158, 164, 170, 172};

#define AVG_LOG_F 1.2465355243460002f
#define INV_BN    0.9999950000374997f

__device__ __forceinline__ float to_tf32(float x) {
    unsigned u;
    asm("cvt.rna.tf32.f32 %0, %1;" : "=r"(u) : "f"(x));
    return __uint_as_float(u);
}

// position of logical k inside its 8-group after pair permutation
__device__ __forceinline__ int posk(int k) {
    return (k & ~7) | (((k & 3) << 1) | ((k >> 2) & 1));
}

__device__ __forceinline__ void mma_tf32(float c[4], unsigned a0, unsigned a1,
                                         unsigned a2, unsigned a3,
                                         unsigned b0, unsigned b1) {
    asm volatile(
        "mma.sync.aligned.m16n8k8.row.col.f32.tf32.tf32.f32 "
        "{%0,%1,%2,%3}, {%4,%5,%6,%7}, {%8,%9}, {%0,%1,%2,%3};\n"
        : "+f"(c[0]), "+f"(c[1]), "+f"(c[2]), "+f"(c[3])
        : "r"(a0), "r"(a1), "r"(a2), "r"(a3), "r"(b0), "r"(b1));
}

#define CP16(dst, src) \
    asm volatile("cp.async.cg.shared.global [%0], [%1], 16;\n" :: "r"(dst), "l"(src))
#define CPCOMMIT() asm volatile("cp.async.commit_group;\n" ::: "memory")
#define CPWAIT(n)  asm volatile("cp.async.wait_group %0;\n" :: "n"(n) : "memory")

__device__ __forceinline__ unsigned smem_u32(const void* p) {
    return (unsigned)__cvta_generic_to_shared(p);
}

// ------- launch 1: atom encoder + zero init + W3 pack (all independent) ----
__global__ void init_kernel(const int* __restrict__ x, const float* __restrict__ emb,
                            const float* __restrict__ W) {
    int flat = threadIdx.y * 70 + threadIdx.x;
    int gtid = blockIdx.x * 280 + flat;
    if (gtid < N_NODES) g_cnt[gtid] = 0;
    if (gtid < N_GRAPHS * D) g_gsum[gtid] = 0.f;
    if (gtid < N_GRAPHS) g_gcnt[gtid] = 0.f;

    // W3 pack into pair-permuted tf32 layout
    if (gtid < 134400) {                      // 4 layers * 33600 float2
        int layer = gtid / 33600;
        int rem = gtid - layer * 33600;
        int kt = rem / 4800; rem -= kt * 4800;
        int g = rem / 960;   rem -= g * 960;
        int col = rem >> 2;
        int l = rem & 3;
        int half = col / 120;
        int cr = col - half * 120;
        int tile = cr >> 3;
        int u = cr & 7;
        int p = tile / 5;
        int jb = tile - p * 5;
        int j = half * 40 + jb * 8 + u;
        int kx = kt * 40 + g * 8 + l;
        float vx = 0.f, vy = 0.f;
        if (j < 70) {
            const float* Wl = W + (size_t)layer * 840 * 70;
            vx = to_tf32(Wl[(size_t)(p * KDIM + kx) * 70 + j]);
            vy = to_tf32(Wl[(size_t)(p * KDIM + kx + 4) * 70 + j]);
        }
        g_w3[gtid * 2]     = vx;
        g_w3[gtid * 2 + 1] = vy;
    }

    int n = blockIdx.x * blockDim.y + threadIdx.y;
    int f = threadIdx.x;
    if (n >= N_NODES) return;
    float s = 0.f;
#pragma unroll
    for (int j = 0; j < 9; j++) {
        int idx = x[n * 9 + j] + c_atom_off[j];
        s += emb[idx * D + f];
    }
    g_h[n * D + f] = s;
}

// ------- launch 2: direct bucket scatter -----------------------------------
__global__ void scatter_kernel(const int* __restrict__ ei) {
    int e = blockIdx.x * blockDim.x + threadIdx.x;
    if (e < N_EDGES) {
        int d = ei[N_EDGES + e];
        int s = ei[e];
        int p = atomicAdd(&g_cnt[d], 1);
        if (p < BCAP) g_bucket[(size_t)d * BCAP + p] = make_int2(e, s);
    }
}

// ------- per-node aggregation (one warp per node) --------------------------
// float2-vectorized loads; writes tf32-rounded, pair-permuted g_agg rows.
__global__ void agg_kernel(const float* __restrict__ ea) {
    int gtid = blockIdx.x * blockDim.x + threadIdx.x;
    int node = gtid >> 5;
    int lane = gtid & 31;
    if (node >= N_NODES) return;

    const float2* hrow = (const float2*)(g_h + (size_t)node * D);
    float2 hm = hrow[lane];
    float2 ht = make_float2(0.f, 0.f);
    if (lane < 3) ht = hrow[32 + lane];

    int cnt0 = g_cnt[node];
    int cnt = (cnt0 < BCAP) ? cnt0 : BCAP;
    const int2* bkt = g_bucket + (size_t)node * BCAP;

    float2 s  = make_float2(0.f, 0.f), q  = make_float2(0.f, 0.f);
    float2 mn = make_float2(3.4e38f, 3.4e38f), mx = make_float2(0.f, 0.f);
    float2 st = make_float2(0.f, 0.f), qt = make_float2(0.f, 0.f);
    float2 mnt = make_float2(3.4e38f, 3.4e38f), mxt = make_float2(0.f, 0.f);

    int2 es = make_int2(0, 0);
    if (cnt > 0) es = bkt[0];
    for (int p = 0; p < cnt; p++) {
        const float2* hs = (const float2*)(g_h + (size_t)es.y * D);
        const float2* er = (const float2*)(ea + (size_t)es.x * D);
        float2 a = hs[lane];
        float2 b2 = er[lane];
        float2 at = make_float2(0.f, 0.f), bt = make_float2(0.f, 0.f);
        if (lane < 3) { at = hs[32 + lane]; bt = er[32 + lane]; }
        if (p + 1 < cnt) es = bkt[p + 1];   // prefetch next (edge, src)

        float m0 = fmaxf(hm.x + a.x + b2.x, 0.f);
        float m1 = fmaxf(hm.y + a.y + b2.y, 0.f);
        s.x += m0; q.x += m0 * m0; mn.x = fminf(mn.x, m0); mx.x = fmaxf(mx.x, m0);
        s.y += m1; q.y += m1 * m1; mn.y = fminf(mn.y, m1); mx.y = fmaxf(mx.y, m1);
        if (lane < 3) {
            float t0 = fmaxf(ht.x + at.x + bt.x, 0.f);
            float t1 = fmaxf(ht.y + at.y + bt.y, 0.f);
            st.x += t0; qt.x += t0 * t0; mnt.x = fminf(mnt.x, t0); mxt.x = fmaxf(mxt.x, t0);
            st.y += t1; qt.y += t1 * t1; mnt.y = fminf(mnt.y, t1); mxt.y = fmaxf(mxt.y, t1);
        }
    }
    float cf = (cnt > 0) ? (float)cnt : 1.f;
    float inv = 1.f / cf;

    float2 me = make_float2(s.x * inv, s.y * inv);
    float2 sd;
    sd.x = sqrtf(fmaxf(q.x * inv - me.x * me.x, 0.f) + 1e-5f);
    sd.y = sqrtf(fmaxf(q.y * inv - me.y * me.y, 0.f) + 1e-5f);
    float2 met = make_float2(st.x * inv, st.y * inv);
    float2 sdt;
    sdt.x = sqrtf(fmaxf(qt.x * inv - met.x * met.x, 0.f) + 1e-5f);
    sdt.y = sqrtf(fmaxf(qt.y * inv - met.y * met.y, 0.f) + 1e-5f);
    if (cnt == 0) {
        mn = make_float2(0.f, 0.f); mx = make_float2(0.f, 0.f);
        mnt = make_float2(0.f, 0.f); mxt = make_float2(0.f, 0.f);
    }

    // permuted tf32 stores: logical k = stat*70 + feat -> row offset posk(k)
    float* arow = g_agg + (size_t)node * KDIM;
    int f0 = 2 * lane;
    arow[posk(f0)]            = to_tf32(me.x);  arow[posk(f0 + 1)]            = to_tf32(me.y);
    arow[posk(70 + f0)]       = to_tf32(mn.x);  arow[posk(70 + f0 + 1)]       = to_tf32(mn.y);
    arow[posk(140 + f0)]      = to_tf32(mx.x);  arow[posk(140 + f0 + 1)]      = to_tf32(mx.y);
    arow[posk(210 + f0)]      = to_tf32(sd.x);  arow[posk(210 + f0 + 1)]      = to_tf32(sd.y);
    if (lane < 3) {
        int ft = 64 + 2 * lane;
        arow[posk(ft)]        = to_tf32(met.x); arow[posk(ft + 1)]        = to_tf32(met.y);
        arow[posk(70 + ft)]   = to_tf32(mnt.x); arow[posk(70 + ft + 1)]   = to_tf32(mnt.y);
        arow[posk(140 + ft)]  = to_tf32(mxt.x); arow[posk(140 + ft + 1)]  = to_tf32(mxt.y);
        arow[posk(210 + ft)]  = to_tf32(sdt.x); arow[posk(210 + ft + 1)]  = to_tf32(sdt.y);
    }
    if (lane == 0) g_amp[node] = logf(cf + 1.f) / AVG_LOG_F;
}

// ---------------- TF32 tensor-core GEMM, cp.async double-buffered ----------
// [64 x 280] @ [280 x 240] per block; 8 warps 4m x 2n (16 rows x 120 cols).
// 35 stages (kt,g); B double-buffered per stage, A double-buffered per kt.
#define GM 64
__global__ __launch_bounds__(256, 2)
void gemm_kernel(int layer,
                 const float* __restrict__ b,
                 const float* __restrict__ gamma, const float* __restrict__ beta) {
    __shared__ float2 As2[2][5 * GM * 4];   // 2 x 10240 B
    __shared__ float2 Bs2[2][240 * 4];      // 2 x  7680 B
    const float4* __restrict__ Ag = (const float4*)g_agg;          // row stride 70 f4
    const float4* __restrict__ Wg = (const float4*)g_w3 + (size_t)layer * 16800;
    int t = threadIdx.x;
    int lane = t & 31, wid = t >> 5;
    int wm = wid & 3, wn = wid >> 2;
    int row0 = blockIdx.x * GM;

    unsigned asb[2] = { smem_u32(&As2[0][0]), smem_u32(&As2[1][0]) };
    unsigned bsb[2] = { smem_u32(&Bs2[0][0]), smem_u32(&Bs2[1][0]) };

    float c[15][4];
#pragma unroll
    for (int i = 0; i < 15; i++)
#pragma unroll
        for (int r = 0; r < 4; r++) c[i][r] = 0.f;

    // ---- async fill helpers (straight 16B copies; layouts prematched) ----
    // A(kt) -> buf: 640 float4. smem f4 idx ((q>>1)*64+r)*2+(q&1); gmem f4 (row0+r)*70 + kt*10 + q
    // B(stage) -> buf: 480 float4 contiguous at Wg + stage*480
#define ISSUE_A(ktv, bi)                                                       \
    for (int idx = t; idx < 640; idx += 256) {                                 \
        int r = idx / 10, qq = idx - 10 * r;                                   \
        CP16(asb[bi] + ((((qq >> 1) * GM + r) * 2 + (qq & 1)) << 4),           \
             Ag + (size_t)(row0 + r) * 70 + (ktv) * 10 + qq);                  \
    }
#define ISSUE_B(sv, bi)                                                        \
    for (int idx = t; idx < 480; idx += 256) {                                 \
        CP16(bsb[bi] + (idx << 4), Wg + (size_t)(sv) * 480 + idx);             \
    }

    // prologue: stage 0 (A0 + B0), stage 1 (B1)
    ISSUE_A(0, 0); ISSUE_B(0, 0); CPCOMMIT();
    ISSUE_B(1, 1); CPCOMMIT();

    int kt = 0, gg = 0;
    for (int s = 0; s < 35; s++) {
        if (s < 34) { CPWAIT(1); } else { CPWAIT(0); }
        __syncthreads();

        const float2* Ab = As2[kt & 1];
        const float2* Bb = Bs2[s & 1];
        float2 A0 = Ab[(gg * GM + wm * 16 + (lane >> 2)) * 4 + (lane & 3)];
        float2 A1 = Ab[(gg * GM + wm * 16 + 8 + (lane >> 2)) * 4 + (lane & 3)];
        unsigned a0 = __float_as_uint(A0.x), a1 = __float_as_uint(A1.x);
        unsigned a2 = __float_as_uint(A0.y), a3 = __float_as_uint(A1.y);
#pragma unroll
        for (int tile = 0; tile < 15; tile++) {
            float2 Bv = Bb[(wn * 120 + tile * 8 + (lane >> 2)) * 4 + (lane & 3)];
            mma_tf32(c[tile], a0, a1, a2, a3,
                     __float_as_uint(Bv.x), __float_as_uint(Bv.y));
        }
        __syncthreads();

        int sn = s + 2;
        if (sn < 35) {
            ISSUE_B(sn, sn & 1);
            if (sn == 5 * (sn / 5)) {            // sn % 5 == 0 -> new kt's A
                int ktn = sn / 5;
                ISSUE_A(ktn, ktn & 1);
            }
            CPCOMMIT();
        }
        if (++gg == 5) { gg = 0; ++kt; }
    }

    // epilogue: combine 3 panels with amp, bias, BN, relu, residual
    int r0 = row0 + wm * 16 + (lane >> 2);
    int r1 = r0 + 8;
    float amp0 = (r0 < N_NODES) ? g_amp[r0] : 1.f;
    float amp1 = (r1 < N_NODES) ? g_amp[r1] : 1.f;
#pragma unroll
    for (int jb = 0; jb < 5; jb++) {
#pragma unroll
        for (int cc = 0; cc < 2; cc++) {
            int j = wn * 40 + jb * 8 + (lane & 3) * 2 + cc;
            if (j < 70) {
                float bj = b[j], gj = gamma[j], btj = beta[j];
                if (r0 < N_NODES) {
                    float comb = c[jb][cc] + amp0 * c[5 + jb][cc] + c[10 + jb][cc] / amp0;
                    float hn = fmaxf((comb + bj) * INV_BN * gj + btj, 0.f);
                    g_h[(size_t)r0 * D + j] += hn;
                }
                if (r1 < N_NODES) {
                    float comb = c[jb][2 + cc] + amp1 * c[5 + jb][2 + cc] + c[10 + jb][2 + cc] / amp1;
                    float hn = fmaxf((comb + bj) * INV_BN * gj + btj, 0.f);
                    g_h[(size_t)r1 * D + j] += hn;
                }
            }
        }
    }
#undef ISSUE_A
#undef ISSUE_B
}

// ---------------- global mean pool -----------------------------------------
__global__ void pool_kernel(const int* __restrict__ batch) {
    int n = blockIdx.x * blockDim.y + threadIdx.y;
    int f = threadIdx.x;
    if (n >= N_NODES) return;
    int gi = batch[n];
    atomicAdd(&g_gsum[gi * D + f], g_h[(size_t)n * D + f]);
    if (f == 0) atomicAdd(&g_gcnt[gi], 1.f);
}

// ---------------- final MLP 70->35->17->1 ----------------------------------
__global__ void mlp_kernel(const float* __restrict__ w1, const float* __restrict__ b1,
                           const float* __restrict__ w2, const float* __restrict__ b2,
                           const float* __restrict__ w3, const float* __restrict__ b3,
                           float* __restrict__ out) {
    __shared__ float sg[70], t1[35], t2[17];
    int gi = blockIdx.x;
    int t = threadIdx.x;
    if (t < 70) {
        float cdenom = fmaxf(g_gcnt[gi], 1.f);
        sg[t] = g_gsum[gi * D + t] / cdenom;
    }
    __syncthreads();
    if (t < 35) {
        float s = b1[t];
        for (int k = 0; k < 70; k++) s += sg[k] * w1[k * 35 + t];
        t1[t] = fmaxf(s, 0.f);
    }
    __syncthreads();
    if (t < 17) {
        float s = b2[t];
        for (int k = 0; k < 35; k++) s += t1[k] * w2[k * 17 + t];
        t2[t] = fmaxf(s, 0.f);
    }
    __syncthreads();
    if (t == 0) {
        float s = b3[0];
        for (int k = 0; k < 17; k++) s += t2[k] * w3[k];
        out[gi] = s;
    }
}

// ---------------- launcher --------------------------------------------------
extern "C" void kernel_launch(void* const* d_in, const int* in_sizes, int n_in,
                              void* d_out, int out_size) {
    const int*   x      = (const int*)d_in[0];
    const int*   ei     = (const int*)d_in[1];
    const float* ea     = (const float*)d_in[2];
    const int*   batch  = (const int*)d_in[3];
    const float* emb    = (const float*)d_in[4];
    const float* post_w = (const float*)d_in[5];
    const float* post_b = (const float*)d_in[6];
    const float* gamma  = (const float*)d_in[7];
    const float* beta   = (const float*)d_in[8];
    const float* w1 = (const float*)d_in[9];
    const float* b1 = (const float*)d_in[10];
    const float* w2 = (const float*)d_in[11];
    const float* b2 = (const float*)d_in[12];
    const float* w3 = (const float*)d_in[13];
    const float* b3 = (const float*)d_in[14];
    float* out = (float*)d_out;

    init_kernel<<<(N_NODES + 3) / 4, dim3(70, 4)>>>(x, emb, post_w);   // 1
    scatter_kernel<<<(N_EDGES + 255) / 256, 256>>>(ei);                // 2

    for (int l = 0; l < 4; l++) {
        agg_kernel<<<(N_NODES * 32 + 255) / 256, 256>>>(ea);           // 3 (l=0)
        gemm_kernel<<<NPAD / GM, 256>>>(                               // 4 (l=0) <- profiled
            l, post_b + l * 70, gamma + l * 70, beta + l * 70);
    }

    pool_kernel<<<(N_NODES + 3) / 4, dim3(70, 4)>>>(batch);
    mlp_kernel<<<N_GRAPHS, 70>>>(w1, b1, w2, b2, w3, b3, out);
}

// round 9
// speedup vs baseline: 1.4480x; 1.0498x over previous
#include <cuda_runtime.h>
#include <math.h>

#define N_NODES  100000
#define N_EDGES  400000
#define N_GRAPHS 4000
#define D        70
#define NP       240
#define KDIM     280
#define BCAP     32           // bucket capacity (P(deg>32) ~ e^-44 for Poisson(4))
#define NPAD     100032       // padded rows (1563 * 64)

// ---------------- scratch (device globals) ---------------------------------
__device__ float g_h[N_NODES * D];
// agg in pair-permuted tf32 layout: value of logical k stored at posk(k) within
// each 280-float row; rows >= N_NODES stay zero (device globals zero-init).
__device__ __align__(16) float g_agg[NPAD * KDIM];
__device__ float g_amp[N_NODES];
__device__ int   g_cnt[N_NODES];
__device__ int2  g_bucket[N_NODES * BCAP];    // (edge id, src node)
__device__ float g_gsum[N_GRAPHS * D];
__device__ float g_gcnt[N_GRAPHS];
// packed tf32 weights: [layer][stage(35)][1920 floats]
//   paired region (448 float4): q = ((h*7+p)*8+r4)*4+l ->
//     (W[k+l][cA], W[k+4+l][cA], W[k+l][cB], W[k+4+l][cB]), cA=h*120+p*16+r4, cB=cA+8
//   leftover (64 float2): f2 = (h*8+r4)*4+l -> (W[k+l][c], W[k+4+l][c]), c=h*120+112+r4
//   k = stage*8
__device__ __align__(16) float g_w3[4 * KDIM * NP];

__constant__ int c_atom_off[9] = {0, 119, 124, 136, 148, 158, 164, 170, 172};

#define AVG_LOG_F 1.2465355243460002f
#define INV_BN    0.9999950000374997f

__device__ __forceinline__ float to_tf32(float x) {
    unsigned u;
    asm("cvt.rna.tf32.f32 %0, %1;" : "=r"(u) : "f"(x));
    return __uint_as_float(u);
}

// position of logical k inside its 8-group after pair permutation
__device__ __forceinline__ int posk(int k) {
    return (k & ~7) | (((k & 3) << 1) | ((k >> 2) & 1));
}

__device__ __forceinline__ void mma_tf32(float c[4], unsigned a0, unsigned a1,
                                         unsigned a2, unsigned a3,
                                         unsigned b0, unsigned b1) {
    asm volatile(
        "mma.sync.aligned.m16n8k8.row.col.f32.tf32.tf32.f32 "
        "{%0,%1,%2,%3}, {%4,%5,%6,%7}, {%8,%9}, {%0,%1,%2,%3};\n"
        : "+f"(c[0]), "+f"(c[1]), "+f"(c[2]), "+f"(c[3])
        : "r"(a0), "r"(a1), "r"(a2), "r"(a3), "r"(b0), "r"(b1));
}

#define CP16(dst, src) \
    asm volatile("cp.async.cg.shared.global [%0], [%1], 16;\n" :: "r"(dst), "l"(src))
#define CP8(dst, src) \
    asm volatile("cp.async.ca.shared.global [%0], [%1], 8;\n" :: "r"(dst), "l"(src))
#define CPCOMMIT() asm volatile("cp.async.commit_group;\n" ::: "memory")
#define CPWAIT(n)  asm volatile("cp.async.wait_group %0;\n" :: "n"(n) : "memory")

__device__ __forceinline__ unsigned smem_u32(const void* p) {
    return (unsigned)__cvta_generic_to_shared(p);
}
__device__ __forceinline__ float4 lds128(unsigned a) {
    float4 v;
    asm volatile("ld.shared.v4.f32 {%0,%1,%2,%3}, [%4];"
                 : "=f"(v.x), "=f"(v.y), "=f"(v.z), "=f"(v.w) : "r"(a));
    return v;
}
__device__ __forceinline__ float2 lds64(unsigned a) {
    float2 v;
    asm volatile("ld.shared.v2.f32 {%0,%1}, [%2];" : "=f"(v.x), "=f"(v.y) : "r"(a));
    return v;
}
#define FU(x) __float_as_uint(x)

// ------- launch 1: atom encoder + zero init + W3 pack (all independent) ----
__global__ void init_kernel(const int* __restrict__ x, const float* __restrict__ emb,
                            const float* __restrict__ W) {
    int flat = threadIdx.y * 70 + threadIdx.x;
    int gtid = blockIdx.x * 280 + flat;
    if (gtid < N_NODES) g_cnt[gtid] = 0;
    if (gtid < N_GRAPHS * D) g_gsum[gtid] = 0.f;
    if (gtid < N_GRAPHS) g_gcnt[gtid] = 0.f;

    // W3 pack into tile-paired tf32 layout (one float per thread)
    if (gtid < 268800) {                      // 4 layers * 35 stages * 1920
        int layer = gtid / 67200;
        int rem = gtid - layer * 67200;
        int st = rem / 1920;
        int f = rem - st * 1920;
        int l, r4, h, dk, col;
        if (f < 1792) {
            int q = f >> 2, comp = f & 3;
            l = q & 3; r4 = (q >> 2) & 7;
            int rest = q >> 5;
            int p = rest % 7; h = rest / 7;
            col = h * 120 + p * 16 + r4 + ((comp >> 1) ? 8 : 0);
            dk = (comp & 1) ? 4 : 0;
        } else {
            int m = f - 1792;
            int f2 = m >> 1, c2 = m & 1;
            l = f2 & 3; r4 = (f2 >> 2) & 7; h = f2 >> 5;
            col = h * 120 + 112 + r4;
            dk = c2 ? 4 : 0;
        }
        int kk = st * 8 + l + dk;
        int cr = col - h * 120;
        int tile = cr >> 3, u = cr & 7;
        int panel = tile / 5, jb = tile - panel * 5;
        int j = h * 40 + jb * 8 + u;
        float v = 0.f;
        if (j < 70)
            v = to_tf32(W[((size_t)layer * 840 + panel * KDIM + kk) * 70 + j]);
        g_w3[gtid] = v;
    }

    int n = blockIdx.x * blockDim.y + threadIdx.y;
    int f = threadIdx.x;
    if (n >= N_NODES) return;
    float s = 0.f;
#pragma unroll
    for (int j = 0; j < 9; j++) {
        int idx = x[n * 9 + j] + c_atom_off[j];
        s += emb[idx * D + f];
    }
    g_h[n * D + f] = s;
}

// ------- launch 2: direct bucket scatter -----------------------------------
__global__ void scatter_kernel(const int* __restrict__ ei) {
    int e = blockIdx.x * blockDim.x + threadIdx.x;
    if (e < N_EDGES) {
        int d = ei[N_EDGES + e];
        int s = ei[e];
        int p = atomicAdd(&g_cnt[d], 1);
        if (p < BCAP) g_bucket[(size_t)d * BCAP + p] = make_int2(e, s);
    }
}

// ------- per-node aggregation (one warp per node) --------------------------
// float2-vectorized loads; writes tf32-rounded, pair-permuted g_agg rows.
__global__ void agg_kernel(const float* __restrict__ ea) {
    int gtid = blockIdx.x * blockDim.x + threadIdx.x;
    int node = gtid >> 5;
    int lane = gtid & 31;
    if (node >= N_NODES) return;

    const float2* hrow = (const float2*)(g_h + (size_t)node * D);
    float2 hm = hrow[lane];
    float2 ht = make_float2(0.f, 0.f);
    if (lane < 3) ht = hrow[32 + lane];

    int cnt0 = g_cnt[node];
    int cnt = (cnt0 < BCAP) ? cnt0 : BCAP;
    const int2* bkt = g_bucket + (size_t)node * BCAP;

    float2 s  = make_float2(0.f, 0.f), q  = make_float2(0.f, 0.f);
    float2 mn = make_float2(3.4e38f, 3.4e38f), mx = make_float2(0.f, 0.f);
    float2 st = make_float2(0.f, 0.f), qt = make_float2(0.f, 0.f);
    float2 mnt = make_float2(3.4e38f, 3.4e38f), mxt = make_float2(0.f, 0.f);

    int2 es = make_int2(0, 0);
    if (cnt > 0) es = bkt[0];
    for (int p = 0; p < cnt; p++) {
        const float2* hs = (const float2*)(g_h + (size_t)es.y * D);
        const float2* er = (const float2*)(ea + (size_t)es.x * D);
        float2 a = hs[lane];
        float2 b2 = er[lane];
        float2 at = make_float2(0.f, 0.f), bt = make_float2(0.f, 0.f);
        if (lane < 3) { at = hs[32 + lane]; bt = er[32 + lane]; }
        if (p + 1 < cnt) es = bkt[p + 1];   // prefetch next (edge, src)

        float m0 = fmaxf(hm.x + a.x + b2.x, 0.f);
        float m1 = fmaxf(hm.y + a.y + b2.y, 0.f);
        s.x += m0; q.x += m0 * m0; mn.x = fminf(mn.x, m0); mx.x = fmaxf(mx.x, m0);
        s.y += m1; q.y += m1 * m1; mn.y = fminf(mn.y, m1); mx.y = fmaxf(mx.y, m1);
        if (lane < 3) {
            float t0 = fmaxf(ht.x + at.x + bt.x, 0.f);
            float t1 = fmaxf(ht.y + at.y + bt.y, 0.f);
            st.x += t0; qt.x += t0 * t0; mnt.x = fminf(mnt.x, t0); mxt.x = fmaxf(mxt.x, t0);
            st.y += t1; qt.y += t1 * t1; mnt.y = fminf(mnt.y, t1); mxt.y = fmaxf(mxt.y, t1);
        }
    }
    float cf = (cnt > 0) ? (float)cnt : 1.f;
    float inv = 1.f / cf;

    float2 me = make_float2(s.x * inv, s.y * inv);
    float2 sd;
    sd.x = sqrtf(fmaxf(q.x * inv - me.x * me.x, 0.f) + 1e-5f);
    sd.y = sqrtf(fmaxf(q.y * inv - me.y * me.y, 0.f) + 1e-5f);
    float2 met = make_float2(st.x * inv, st.y * inv);
    float2 sdt;
    sdt.x = sqrtf(fmaxf(qt.x * inv - met.x * met.x, 0.f) + 1e-5f);
    sdt.y = sqrtf(fmaxf(qt.y * inv - met.y * met.y, 0.f) + 1e-5f);
    if (cnt == 0) {
        mn = make_float2(0.f, 0.f); mx = make_float2(0.f, 0.f);
        mnt = make_float2(0.f, 0.f); mxt = make_float2(0.f, 0.f);
    }

    // permuted tf32 stores: logical k = stat*70 + feat -> row offset posk(k)
    float* arow = g_agg + (size_t)node * KDIM;
    int f0 = 2 * lane;
    arow[posk(f0)]            = to_tf32(me.x);  arow[posk(f0 + 1)]            = to_tf32(me.y);
    arow[posk(70 + f0)]       = to_tf32(mn.x);  arow[posk(70 + f0 + 1)]       = to_tf32(mn.y);
    arow[posk(140 + f0)]      = to_tf32(mx.x);  arow[posk(140 + f0 + 1)]      = to_tf32(mx.y);
    arow[posk(210 + f0)]      = to_tf32(sd.x);  arow[posk(210 + f0 + 1)]      = to_tf32(sd.y);
    if (lane < 3) {
        int ft = 64 + 2 * lane;
        arow[posk(ft)]        = to_tf32(met.x); arow[posk(ft + 1)]        = to_tf32(met.y);
        arow[posk(70 + ft)]   = to_tf32(mnt.x); arow[posk(70 + ft + 1)]   = to_tf32(mnt.y);
        arow[posk(140 + ft)]  = to_tf32(mxt.x); arow[posk(140 + ft + 1)]  = to_tf32(mxt.y);
        arow[posk(210 + ft)]  = to_tf32(sdt.x); arow[posk(210 + ft + 1)]  = to_tf32(sdt.y);
    }
    if (lane == 0) g_amp[node] = logf(cf + 1.f) / AVG_LOG_F;
}

// ---------------- TF32 tensor-core GEMM, 1-barrier pipelined ---------------
// [64 x 280] @ [280 x 240]; 8 warps 4m x 2n (16 rows x 120 cols each).
// B triple-buffered, A double-buffered; LDS.128 fragment loads.
#define GM 64
__global__ __launch_bounds__(256, 2)
void gemm_kernel(int layer,
                 const float* __restrict__ b,
                 const float* __restrict__ gamma, const float* __restrict__ beta) {
    __shared__ __align__(16) float4 Asm[2][640];   // [kt&1]: ((g*4+rt)*8+row8)*4+l
    __shared__ __align__(16) float4 Bsm[3][480];   // [s%3]: stage block (1920 floats)
    const float* __restrict__ Ag = g_agg;
    const float4* __restrict__ Wg = (const float4*)g_w3 + (size_t)layer * 16800;
    int t = threadIdx.x;
    int lane = t & 31, wid = t >> 5;
    int wm = wid & 3, wn = wid >> 2;
    int row0 = blockIdx.x * GM;

    unsigned ab0 = smem_u32(&Asm[0][0]), ab1 = smem_u32(&Asm[1][0]);
    unsigned bb0 = smem_u32(&Bsm[0][0]), bb1 = smem_u32(&Bsm[1][0]), bb2 = smem_u32(&Bsm[2][0]);

    float c[15][4];
#pragma unroll
    for (int i = 0; i < 15; i++)
#pragma unroll
        for (int r = 0; r < 4; r++) c[i][r] = 0.f;

    // A fill: 1280 8B copies. f4 = ((g*4+rt)*8+row8)*4+l ; halves: row r / r+8.
#define ISSUE_A(ktv, base)                                                       \
    for (int idx = t; idx < 1280; idx += 256) {                                  \
        int f4i = idx >> 1, hf = idx & 1;                                        \
        int l = f4i & 3, row8 = (f4i >> 2) & 7, rt = (f4i >> 5) & 3, g = f4i >> 7; \
        int r = rt * 16 + row8 + hf * 8;                                         \
        CP8((base) + f4i * 16 + hf * 8,                                          \
            Ag + (size_t)(row0 + r) * KDIM + (ktv) * 40 + g * 8 + 2 * l);        \
    }
    // B fill: straight 480 16B copies (gmem layout == smem layout)
#define ISSUE_B(sv, base)                                                        \
    for (int idx = t; idx < 480; idx += 256)                                     \
        CP16((base) + (idx << 4), Wg + (size_t)(sv) * 480 + idx);

    // per-lane fragment offsets
    unsigned aoff  = ((wm * 8 + (lane >> 2)) * 4 + (lane & 3)) * 16;
    unsigned boffp = wn * 3584 + (lane >> 2) * 64 + (lane & 3) * 16;
    unsigned bofft = 7168 + wn * 256 + (lane >> 2) * 32 + (lane & 3) * 8;

    // prologue
    ISSUE_A(0, ab0); ISSUE_B(0, bb0); CPCOMMIT();
    ISSUE_B(1, bb1); CPCOMMIT();

    unsigned acur = ab0;
    unsigned bprev = bb2, bcur = bb0, bnext = bb1;
    int gg = 0, kt = 0;

    for (int s = 0; s < 35; s++) {
        if (s < 34) { CPWAIT(1); } else { CPWAIT(0); }
        __syncthreads();

        int sn = s + 2;
        if (sn < 35) {
            ISSUE_B(sn, bprev);
            if (sn == 5 * (sn / 5)) {
                int ktn = sn / 5;
                ISSUE_A(ktn, (ktn & 1) ? ab1 : ab0);
            }
            CPCOMMIT();
        }

        float4 Av = lds128(acur + aoff + (gg << 11));
        unsigned a0 = FU(Av.x), a2 = FU(Av.y), a1 = FU(Av.z), a3 = FU(Av.w);
        unsigned bbase = bcur + boffp;
#pragma unroll
        for (int p = 0; p < 7; p++) {
            float4 Bv = lds128(bbase + p * 512);
            mma_tf32(c[2 * p],     a0, a1, a2, a3, FU(Bv.x), FU(Bv.y));
            mma_tf32(c[2 * p + 1], a0, a1, a2, a3, FU(Bv.z), FU(Bv.w));
        }
        float2 Bt = lds64(bcur + bofft);
        mma_tf32(c[14], a0, a1, a2, a3, FU(Bt.x), FU(Bt.y));

        unsigned tmp = bprev; bprev = bcur; bcur = bnext; bnext = tmp;
        if (++gg == 5) { gg = 0; ++kt; acur = (kt & 1) ? ab1 : ab0; }
    }

    // epilogue: combine 3 panels with amp, bias, BN, relu, residual
    int r0 = row0 + wm * 16 + (lane >> 2);
    int r1 = r0 + 8;
    float amp0 = (r0 < N_NODES) ? g_amp[r0] : 1.f;
    float amp1 = (r1 < N_NODES) ? g_amp[r1] : 1.f;
#pragma unroll
    for (int jb = 0; jb < 5; jb++) {
#pragma unroll
        for (int cc = 0; cc < 2; cc++) {
            int j = wn * 40 + jb * 8 + (lane & 3) * 2 + cc;
            if (j < 70) {
                float bj = b[j], gj = gamma[j], btj = beta[j];
                if (r0 < N_NODES) {
                    float comb = c[jb][cc] + amp0 * c[5 + jb][cc] + c[10 + jb][cc] / amp0;
                    float hn = fmaxf((comb + bj) * INV_BN * gj + btj, 0.f);
                    g_h[(size_t)r0 * D + j] += hn;
                }
                if (r1 < N_NODES) {
                    float comb = c[jb][2 + cc] + amp1 * c[5 + jb][2 + cc] + c[10 + jb][2 + cc] / amp1;
                    float hn = fmaxf((comb + bj) * INV_BN * gj + btj, 0.f);
                    g_h[(size_t)r1 * D + j] += hn;
                }
            }
        }
    }
#undef ISSUE_A
#undef ISSUE_B
}

// ---------------- global mean pool -----------------------------------------
__global__ void pool_kernel(const int* __restrict__ batch) {
    int n = blockIdx.x * blockDim.y + threadIdx.y;
    int f = threadIdx.x;
    if (n >= N_NODES) return;
    int gi = batch[n];
    atomicAdd(&g_gsum[gi * D + f], g_h[(size_t)n * D + f]);
    if (f == 0) atomicAdd(&g_gcnt[gi], 1.f);
}

// ---------------- final MLP 70->35->17->1 ----------------------------------
__global__ void mlp_kernel(const float* __restrict__ w1, const float* __restrict__ b1,
                           const float* __restrict__ w2, const float* __restrict__ b2,
                           const float* __restrict__ w3, const float* __restrict__ b3,
                           float* __restrict__ out) {
    __shared__ float sg[70], t1[35], t2[17];
    int gi = blockIdx.x;
    int t = threadIdx.x;
    if (t < 70) {
        float cdenom = fmaxf(g_gcnt[gi], 1.f);
        sg[t] = g_gsum[gi * D + t] / cdenom;
    }
    __syncthreads();
    if (t < 35) {
        float s = b1[t];
        for (int k = 0; k < 70; k++) s += sg[k] * w1[k * 35 + t];
        t1[t] = fmaxf(s, 0.f);
    }
    __syncthreads();
    if (t < 17) {
        float s = b2[t];
        for (int k = 0; k < 35; k++) s += t1[k] * w2[k * 17 + t];
        t2[t] = fmaxf(s, 0.f);
    }
    __syncthreads();
    if (t == 0) {
        float s = b3[0];
        for (int k = 0; k < 17; k++) s += t2[k] * w3[k];
        out[gi] = s;
    }
}

// ---------------- launcher --------------------------------------------------
extern "C" void kernel_launch(void* const* d_in, const int* in_sizes, int n_in,
                              void* d_out, int out_size) {
    const int*   x      = (const int*)d_in[0];
    const int*   ei     = (const int*)d_in[1];
    const float* ea     = (const float*)d_in[2];
    const int*   batch  = (const int*)d_in[3];
    const float* emb    = (const float*)d_in[4];
    const float* post_w = (const float*)d_in[5];
    const float* post_b = (const float*)d_in[6];
    const float* gamma  = (const float*)d_in[7];
    const float* beta   = (const float*)d_in[8];
    const float* w1 = (const float*)d_in[9];
    const float* b1 = (const float*)d_in[10];
    const float* w2 = (const float*)d_in[11];
    const float* b2 = (const float*)d_in[12];
    const float* w3 = (const float*)d_in[13];
    const float* b3 = (const float*)d_in[14];
    float* out = (float*)d_out;

    init_kernel<<<(N_NODES + 3) / 4, dim3(70, 4)>>>(x, emb, post_w);   // 1
    scatter_kernel<<<(N_EDGES + 255) / 256, 256>>>(ei);                // 2

    for (int l = 0; l < 4; l++) {
        agg_kernel<<<(N_NODES * 32 + 255) / 256, 256>>>(ea);           // 3 (l=0)
        gemm_kernel<<<NPAD / GM, 256>>>(                               // 4 (l=0) <- profiled
            l, post_b + l * 70, gamma + l * 70, beta + l * 70);
    }

    pool_kernel<<<(N_NODES + 3) / 4, dim3(70, 4)>>>(batch);
    mlp_kernel<<<N_GRAPHS, 70>>>(w1, b1, w2, b2, w3, b3, out);
}